// round 11
// baseline (speedup 1.0000x reference)
#include <cuda_runtime.h>
#include <cuda_bf16.h>
#include <cstdint>

// ---------------- problem shapes (fixed) ----------------
#define N_ROWS 8192
#define M_ROWS 16384
#define DIM    256

#define BM 64
#define BN 128
#define SPLITS 16
#define BROWS (M_ROWS / SPLITS)     // 1024
#define NBT   (BROWS / BN)          // 8 tiles
#define KCH   128                   // int8 K-elems per chunk (128B/row)
#define CPT   (DIM / KCH)           // 2 chunks per tile
#define TOTCH (NBT * CPT)           // 16
#define NBUF  4

// smem (uint32 words): A = 64 rows x 64 words (16KB); B = 4 bufs x 128 rows x 32 words (64KB)
#define AW 64
#define BW 32
#define SMEM_WORDS (BM * AW + NBUF * BN * BW)   // 4096 + 16384 = 20480
#define SMEM_BYTES (SMEM_WORDS * 4)             // 81920 -> 2 CTAs/SM

// ---------------- scratch ----------------
__device__ float        g_An[N_ROWS * DIM];
__device__ float        g_Bn[M_ROWS * DIM];
__device__ signed char  g_Ab[N_ROWS * DIM];
__device__ signed char  g_Bb[M_ROWS * DIM];
__device__ float        g_partv[N_ROWS * SPLITS * 3];
__device__ int          g_parti[N_ROWS * SPLITS * 3];

// ---------------- helpers ----------------
__device__ __forceinline__ uint32_t smem_u32(const void* p) {
    uint32_t a;
    asm("{ .reg .u64 t; cvta.to.shared.u64 t, %1; cvt.u32.u64 %0, t; }" : "=r"(a) : "l"(p));
    return a;
}
__device__ __forceinline__ void cp_async16(uint32_t dst, const void* src) {
    asm volatile("cp.async.cg.shared.global [%0], [%1], 16;" :: "r"(dst), "l"(src));
}
#define CP_COMMIT()  asm volatile("cp.async.commit_group;" ::: "memory")
#define CP_WAIT(n)   asm volatile("cp.async.wait_group %0;" :: "n"(n) : "memory")

__device__ __forceinline__ void ldm_x4(uint32_t* r, uint32_t addr) {
    asm volatile("ldmatrix.sync.aligned.m8n8.x4.shared.b16 {%0,%1,%2,%3}, [%4];"
                 : "=r"(r[0]), "=r"(r[1]), "=r"(r[2]), "=r"(r[3]) : "r"(addr));
}
__device__ __forceinline__ void mma_s8(int* d, const uint32_t* a, const uint32_t* b) {
    asm volatile(
        "mma.sync.aligned.m16n8k32.row.col.s32.s8.s8.s32 "
        "{%0,%1,%2,%3},{%4,%5,%6,%7},{%8,%9},{%0,%1,%2,%3};"
        : "+r"(d[0]), "+r"(d[1]), "+r"(d[2]), "+r"(d[3])
        : "r"(a[0]), "r"(a[1]), "r"(a[2]), "r"(a[3]), "r"(b[0]), "r"(b[1]));
}

// ---------------- row L2 normalization: write fp32 (exact) + int8 ----------------
__global__ void normalize_rows(const float* __restrict__ in,
                               float* __restrict__ outf,
                               signed char* __restrict__ outb) {
    int row = blockIdx.x, tid = threadIdx.x;
    float v = in[row * DIM + tid];
    float s = v * v;
    #pragma unroll
    for (int o = 16; o > 0; o >>= 1) s += __shfl_xor_sync(0xFFFFFFFFu, s, o);
    __shared__ float red[8];
    if ((tid & 31) == 0) red[tid >> 5] = s;
    __syncthreads();
    __shared__ float tot;
    if (tid < 32) {
        float t = (tid < 8) ? red[tid] : 0.0f;
        #pragma unroll
        for (int o = 4; o > 0; o >>= 1) t += __shfl_xor_sync(0xFFFFFFFFu, t, o);
        if (tid == 0) tot = t;
    }
    __syncthreads();
    float y = v * rsqrtf(tot);
    outf[row * DIM + tid] = y;
    int q = __float2int_rn(y * 127.0f);
    q = max(-127, min(127, q));
    outb[row * DIM + tid] = (signed char)q;
}

// ---------------- int8 mma GEMM (ldmatrix, occ=2) + top-3 with indices ----------------
__global__ void __launch_bounds__(256, 2)
gemm_top3(const signed char* __restrict__ Ab, const signed char* __restrict__ Bb,
          float* __restrict__ partv, int* __restrict__ parti) {
    extern __shared__ uint32_t smem[];
    uint32_t* sA = smem;
    uint32_t* sB = smem + BM * AW;
    const uint32_t sAu = smem_u32(sA);
    const uint32_t sBu = smem_u32(sB);

    const int tid  = threadIdx.x;
    const int w    = tid >> 5, lane = tid & 31;
    const int ty   = lane >> 2, tx = lane & 3;
    const int warpM = w >> 2, warpN = w & 3;      // 2 x 4 warp grid

    const int aBase = blockIdx.x * BM;
    const int bBase = blockIdx.y * BROWS;

    // ---- A tile: 64 rows x 256 int8 (two 128B swizzle blocks per row) ----
    #pragma unroll 4
    for (int i = tid; i < BM * 16; i += 256) {          // 16B units
        int r = i >> 4, f = i & 15;                     // f: unit within row
        uint32_t dw = (uint32_t)(r * AW + ((f >> 3) << 5) + ((4 * (f & 7)) ^ ((r & 7) << 2)));
        cp_async16(sAu + dw * 4, Ab + (size_t)(aBase + r) * DIM + f * 16);
    }
    CP_COMMIT();

    auto issueB = [&](int c) {
        int t = c >> 1, kc = c & 1, buf = c & 3;
        #pragma unroll 4
        for (int i = tid; i < BN * 8; i += 256) {       // 16B units (128B/row)
            int n = i >> 3, f = i & 7;
            uint32_t dw = (uint32_t)(buf * BN * BW + n * BW + ((4 * f) ^ ((n & 7) << 2)));
            cp_async16(sBu + dw * 4,
                       Bb + (size_t)(bBase + t * BN + n) * DIM + kc * KCH + f * 16);
        }
        CP_COMMIT();
    };

    issueB(0); issueB(1); issueB(2);

    // ---- precompute ldmatrix per-lane addresses ----
    uint32_t aAddrBase[2], aSw[2];
    {
        int rl = warpM * 32 + (lane & 15);
        #pragma unroll
        for (int m = 0; m < 2; m++) {
            int r = rl + m * 16;
            aAddrBase[m] = sAu + (uint32_t)(r * AW) * 4u;
            aSw[m] = (uint32_t)((r & 7) << 2);
        }
    }
    const uint32_t khA4 = (uint32_t)((lane >> 4) << 2);
    uint32_t bAddrBase[2], bSw[2];
    {
        int nl = warpN * 32 + ((lane >> 4) << 3) + (lane & 7);
        #pragma unroll
        for (int p = 0; p < 2; p++) {
            int n = nl + p * 16;
            bAddrBase[p] = (uint32_t)(n * BW) * 4u;
            bSw[p] = (uint32_t)((n & 7) << 2);
        }
    }
    const uint32_t khB4 = (uint32_t)(((lane >> 3) & 1) << 2);

    int acc[2][4][4];
    #pragma unroll
    for (int m = 0; m < 2; m++)
        #pragma unroll
        for (int nt = 0; nt < 4; nt++)
            #pragma unroll
            for (int q = 0; q < 4; q++) acc[m][nt][q] = 0;

    int s0[4], s1[4], s2[4];
    int i0[4], i1[4], i2[4];
    #pragma unroll
    for (int i = 0; i < 4; i++) {
        s0[i] = -0x7FFFFFFF; s1[i] = -0x7FFFFFFF; s2[i] = -0x7FFFFFFF;
        i0[i] = 0; i1[i] = 0; i2[i] = 0;
    }

    for (int c = 0; c < TOTCH; c++) {
        CP_WAIT(2);                  // group c complete
        __syncthreads();
        if (c + 3 < TOTCH) issueB(c + 3);
        else CP_COMMIT();

        const uint32_t cb32 = (uint32_t)((c & 1) * 32);   // A 128B-block (words)
        const uint32_t bBufByte = sBu + (uint32_t)((c & 3) * BN * BW) * 4u;

        #pragma unroll
        for (int ks = 0; ks < 4; ks++) {                  // 4 x k32 per 128B chunk
            const uint32_t ksw = (uint32_t)(ks * 8);      // 32B in words
            uint32_t a[2][4];
            #pragma unroll
            for (int m = 0; m < 2; m++) {
                uint32_t woff = cb32 + ((ksw + khA4) ^ aSw[m]);
                ldm_x4(a[m], aAddrBase[m] + (woff << 2));
            }
            uint32_t bq[8];
            #pragma unroll
            for (int p = 0; p < 2; p++) {
                uint32_t woff = (ksw + khB4) ^ bSw[p];
                ldm_x4(&bq[p * 4], bBufByte + bAddrBase[p] + (woff << 2));
            }
            #pragma unroll
            for (int m = 0; m < 2; m++)
                #pragma unroll
                for (int nt = 0; nt < 4; nt++)
                    mma_s8(acc[m][nt], a[m], &bq[nt * 2]);
        }

        if ((c & 1) == 1) {
            const int tcol = bBase + (c >> 1) * BN + warpN * 32 + tx * 2;
            #pragma unroll
            for (int m = 0; m < 2; m++) {
                #pragma unroll
                for (int h = 0; h < 2; h++) {
                    const int sl = m * 2 + h;
                    int bm = acc[m][0][h * 2];
                    #pragma unroll
                    for (int nt = 0; nt < 4; nt++) {
                        bm = max(bm, acc[m][nt][h * 2 + 0]);
                        bm = max(bm, acc[m][nt][h * 2 + 1]);
                    }
                    if (bm > s2[sl]) {
                        #pragma unroll
                        for (int nt = 0; nt < 4; nt++) {
                            #pragma unroll
                            for (int p = 0; p < 2; p++) {
                                int v = acc[m][nt][h * 2 + p];
                                int col = tcol + nt * 8 + p;
                                if (v > s2[sl]) {
                                    if (v > s1[sl]) {
                                        if (v > s0[sl]) {
                                            s2[sl] = s1[sl]; i2[sl] = i1[sl];
                                            s1[sl] = s0[sl]; i1[sl] = i0[sl];
                                            s0[sl] = v;      i0[sl] = col;
                                        } else {
                                            s2[sl] = s1[sl]; i2[sl] = i1[sl];
                                            s1[sl] = v;      i1[sl] = col;
                                        }
                                    } else {
                                        s2[sl] = v; i2[sl] = col;
                                    }
                                }
                            }
                        }
                    }
                }
            }
            #pragma unroll
            for (int m = 0; m < 2; m++)
                #pragma unroll
                for (int nt = 0; nt < 4; nt++)
                    #pragma unroll
                    for (int q = 0; q < 4; q++) acc[m][nt][q] = 0;
        }
    }

    // ---- CTA-level merge: 16 contributors per row -> top-3 (score+idx) ----
    __syncthreads();
    int* candV = (int*)smem;                     // [64][16][3]
    int* candI = (int*)smem + 3072;              // [64][16][3]
    #pragma unroll
    for (int m = 0; m < 2; m++) {
        #pragma unroll
        for (int h = 0; h < 2; h++) {
            const int sl = m * 2 + h;
            int row = warpM * 32 + m * 16 + h * 8 + ty;
            int ct  = warpN * 4 + tx;
            int o = (row * 16 + ct) * 3;
            candV[o + 0] = s0[sl]; candV[o + 1] = s1[sl]; candV[o + 2] = s2[sl];
            candI[o + 0] = i0[sl]; candI[o + 1] = i1[sl]; candI[o + 2] = i2[sl];
        }
    }
    __syncthreads();
    if (tid < BM) {
        const int* pv = candV + tid * 48;
        const int* pi = candI + tid * 48;
        int t0 = -0x7FFFFFFF, t1 = -0x7FFFFFFF, t2 = -0x7FFFFFFF;
        int j0 = 0, j1 = 0, j2 = 0;
        #pragma unroll
        for (int i = 0; i < 48; i++) {
            int v = pv[i]; int ix = pi[i];
            if (v > t2) {
                if (v > t1) {
                    if (v > t0) { t2 = t1; j2 = j1; t1 = t0; j1 = j0; t0 = v; j0 = ix; }
                    else        { t2 = t1; j2 = j1; t1 = v;  j1 = ix; }
                } else          { t2 = v; j2 = ix; }
            }
        }
        size_t row = (size_t)(blockIdx.x * BM + tid);
        size_t o = (row * SPLITS + blockIdx.y) * 3;
        partv[o + 0] = (float)t0; partv[o + 1] = (float)t1; partv[o + 2] = (float)t2;
        parti[o + 0] = j0; parti[o + 1] = j1; parti[o + 2] = j2;
    }
}

// ---------------- final: top-8 of 48 candidates, exact fp32 rescore, mean top-3 ----
__device__ __forceinline__ unsigned long long mk_key(float v, int idx) {
    uint32_t u = __float_as_uint(v);
    u = (u & 0x80000000u) ? ~u : (u | 0x80000000u);
    return ((unsigned long long)u << 32) | (uint32_t)idx;
}

__global__ void rescore_top3(const float* __restrict__ partv, const int* __restrict__ parti,
                             const float* __restrict__ An, const float* __restrict__ Bn,
                             float* __restrict__ out) {
    const int warp = (blockIdx.x * blockDim.x + threadIdx.x) >> 5;
    const int lane = threadIdx.x & 31;
    if (warp >= N_ROWS) return;
    const int row = warp;

    const float* pv = partv + (size_t)row * 48;
    const int*   pi = parti + (size_t)row * 48;
    unsigned long long k0 = mk_key(pv[lane], pi[lane]);
    unsigned long long k1 = (lane < 16) ? mk_key(pv[32 + lane], pi[32 + lane]) : 0ull;

    int win[8];
    #pragma unroll
    for (int r = 0; r < 8; r++) {
        unsigned long long m = (k0 > k1) ? k0 : k1;
        #pragma unroll
        for (int o = 16; o > 0; o >>= 1) {
            unsigned long long t = __shfl_xor_sync(0xFFFFFFFFu, m, o);
            if (t > m) m = t;
        }
        win[r] = (int)(uint32_t)m;
        if (k0 == m) k0 = 0ull;
        if (k1 == m) k1 = 0ull;
    }

    const float4* a4 = (const float4*)(An + (size_t)row * DIM);
    float4 av0 = a4[lane * 2], av1 = a4[lane * 2 + 1];

    float dots[8];
    #pragma unroll
    for (int j = 0; j < 8; j++) {
        const float4* b4 = (const float4*)(Bn + (size_t)win[j] * DIM);
        float4 b0 = b4[lane * 2], b1 = b4[lane * 2 + 1];
        float p = av0.x * b0.x + av0.y * b0.y + av0.z * b0.z + av0.w * b0.w
                + av1.x * b1.x + av1.y * b1.y + av1.z * b1.z + av1.w * b1.w;
        #pragma unroll
        for (int o = 16; o > 0; o >>= 1) p += __shfl_xor_sync(0xFFFFFFFFu, p, o);
        dots[j] = p;
    }

    if (lane == 0) {
        float t0 = -2.0f, t1 = -2.0f, t2 = -2.0f;
        #pragma unroll
        for (int j = 0; j < 8; j++) {
            float v = dots[j];
            t2 = fmaxf(t2, fminf(v, t1));
            t1 = fmaxf(t1, fminf(v, t0));
            t0 = fmaxf(t0, v);
        }
        out[row] = (t0 + t1 + t2) * (1.0f / 3.0f);
    }
}

// ---------------- launcher ----------------
extern "C" void kernel_launch(void* const* d_in, const int* in_sizes, int n_in,
                              void* d_out, int out_size) {
    const float* A = (const float*)d_in[0];
    const float* B = (const float*)d_in[1];
    float* out = (float*)d_out;

    float* An; cudaGetSymbolAddress((void**)&An, g_An);
    float* Bn; cudaGetSymbolAddress((void**)&Bn, g_Bn);
    signed char* Ab; cudaGetSymbolAddress((void**)&Ab, g_Ab);
    signed char* Bb; cudaGetSymbolAddress((void**)&Bb, g_Bb);
    float* pv; cudaGetSymbolAddress((void**)&pv, g_partv);
    int*   pi; cudaGetSymbolAddress((void**)&pi, g_parti);

    cudaFuncSetAttribute(gemm_top3, cudaFuncAttributeMaxDynamicSharedMemorySize, SMEM_BYTES);

    normalize_rows<<<N_ROWS, DIM>>>(A, An, Ab);
    normalize_rows<<<M_ROWS, DIM>>>(B, Bn, Bb);

    dim3 grid(N_ROWS / BM, SPLITS);
    gemm_top3<<<grid, 256, SMEM_BYTES>>>(Ab, Bb, pv, pi);

    rescore_top3<<<N_ROWS * 32 / 256, 256>>>(pv, pi, An, Bn, out);
}

// round 12
// speedup vs baseline: 1.1875x; 1.1875x over previous
#include <cuda_runtime.h>
#include <cuda_bf16.h>
#include <cstdint>

// ---------------- problem shapes (fixed) ----------------
#define N_ROWS 8192
#define M_ROWS 16384
#define DIM    256

#define BM 64
#define BN 128
#define SPLITS 16
#define BROWS (M_ROWS / SPLITS)     // 1024
#define NBT   (BROWS / BN)          // 8 tiles
#define KCH   64                    // bf16 K-elems per chunk (128B/row)
#define CPT   (DIM / KCH)           // 4 chunks per tile
#define TOTCH (NBT * CPT)           // 32

// smem (uint32 words): A = 64 x 128 (32KB); per-warp B: 8 warps x 2 bufs x 32 rows x 32 words (64KB)
#define AW 128
#define BW 32
#define WARP_B_WORDS (2 * 32 * BW)              // 2048 words = 8KB per warp
#define SMEM_WORDS (BM * AW + 8 * WARP_B_WORDS) // 8192 + 16384 = 24576
#define SMEM_BYTES (SMEM_WORDS * 4)             // 98304 -> 2 CTAs/SM

// ---------------- scratch ----------------
__device__ float          g_An[N_ROWS * DIM];
__device__ float          g_Bn[M_ROWS * DIM];
__device__ __nv_bfloat16  g_Ah[N_ROWS * DIM];
__device__ __nv_bfloat16  g_Bh[M_ROWS * DIM];
__device__ float          g_partv[N_ROWS * SPLITS * 3];
__device__ int            g_parti[N_ROWS * SPLITS * 3];

// ---------------- helpers ----------------
__device__ __forceinline__ uint32_t smem_u32(const void* p) {
    uint32_t a;
    asm("{ .reg .u64 t; cvta.to.shared.u64 t, %1; cvt.u32.u64 %0, t; }" : "=r"(a) : "l"(p));
    return a;
}
__device__ __forceinline__ void cp_async16(uint32_t dst, const void* src) {
    asm volatile("cp.async.cg.shared.global [%0], [%1], 16;" :: "r"(dst), "l"(src));
}
#define CP_COMMIT()  asm volatile("cp.async.commit_group;" ::: "memory")
#define CP_WAIT(n)   asm volatile("cp.async.wait_group %0;" :: "n"(n) : "memory")

__device__ __forceinline__ void ldm_x4(uint32_t* r, uint32_t addr) {
    asm volatile("ldmatrix.sync.aligned.m8n8.x4.shared.b16 {%0,%1,%2,%3}, [%4];"
                 : "=r"(r[0]), "=r"(r[1]), "=r"(r[2]), "=r"(r[3]) : "r"(addr));
}
__device__ __forceinline__ void mma_bf16(float* d, const uint32_t* a, const uint32_t* b) {
    asm volatile(
        "mma.sync.aligned.m16n8k16.row.col.f32.bf16.bf16.f32 "
        "{%0,%1,%2,%3},{%4,%5,%6,%7},{%8,%9},{%0,%1,%2,%3};"
        : "+f"(d[0]), "+f"(d[1]), "+f"(d[2]), "+f"(d[3])
        : "r"(a[0]), "r"(a[1]), "r"(a[2]), "r"(a[3]), "r"(b[0]), "r"(b[1]));
}

// ---------------- row L2 normalization: write fp32 (exact) + bf16 ----------------
__global__ void normalize_rows(const float* __restrict__ in,
                               float* __restrict__ outf,
                               __nv_bfloat16* __restrict__ outh) {
    int row = blockIdx.x, tid = threadIdx.x;
    float v = in[row * DIM + tid];
    float s = v * v;
    #pragma unroll
    for (int o = 16; o > 0; o >>= 1) s += __shfl_xor_sync(0xFFFFFFFFu, s, o);
    __shared__ float red[8];
    if ((tid & 31) == 0) red[tid >> 5] = s;
    __syncthreads();
    __shared__ float tot;
    if (tid < 32) {
        float t = (tid < 8) ? red[tid] : 0.0f;
        #pragma unroll
        for (int o = 4; o > 0; o >>= 1) t += __shfl_xor_sync(0xFFFFFFFFu, t, o);
        if (tid == 0) tot = t;
    }
    __syncthreads();
    float y = v * rsqrtf(tot);
    outf[row * DIM + tid] = y;
    outh[row * DIM + tid] = __float2bfloat16(y);
}

// ---------------- bf16 mma GEMM, per-warp barrier-free B pipeline + top-3 ----------------
__global__ void __launch_bounds__(256, 2)
gemm_top3(const __nv_bfloat16* __restrict__ Ah, const __nv_bfloat16* __restrict__ Bh,
          float* __restrict__ partv, int* __restrict__ parti) {
    extern __shared__ uint32_t smem[];
    uint32_t* sA = smem;
    const uint32_t sAu = smem_u32(sA);

    const int tid  = threadIdx.x;
    const int w    = tid >> 5, lane = tid & 31;
    const int ty   = lane >> 2, tx = lane & 3;
    const int warpM = w >> 2, warpN = w & 3;      // 2 x 4 warp grid

    uint32_t* sBw = smem + BM * AW + w * WARP_B_WORDS;   // this warp's B ring
    const uint32_t sBwu = smem_u32(sBw);

    const int aBase = blockIdx.x * BM;
    const int bBase = blockIdx.y * BROWS;

    // ---- A tile: 64 rows x 256 bf16; word-swizzle iw' = iw ^ ((r&7)<<2) ----
    #pragma unroll 4
    for (int i = tid; i < BM * 32; i += 256) {          // 16B units
        int r = i >> 5, f = i & 31;
        uint32_t dw = (uint32_t)(r * AW + ((4 * f) ^ ((r & 7) << 2)));
        cp_async16(sAu + dw * 4, Ah + (size_t)(aBase + r) * DIM + f * 8);
    }
    CP_COMMIT();                                         // group: A

    // ---- per-warp B chunk issue: 32 rows (this warp's warpN slice) x 64 K ----
    const int bRowBase = bBase + warpN * 32;             // + tile*BN
    auto issueB = [&](int c) {
        int t = c >> 2, kc = c & 3, buf = c & 1;
        #pragma unroll
        for (int l = 0; l < 8; l++) {
            int u = lane + l * 32;                       // 0..255 16B units
            int n = u >> 3, f = u & 7;                   // local row, unit in row
            uint32_t dw = (uint32_t)(buf * 1024 + n * BW + ((4 * f) ^ ((n & 7) << 2)));
            cp_async16(sBwu + dw * 4,
                       Bh + (size_t)(bRowBase + t * BN + n) * DIM + kc * KCH + f * 8);
        }
        CP_COMMIT();
    };

    issueB(0); issueB(1);

    // wait for A + B0 (<=1 pending), then CTA barrier for A cross-warp visibility
    CP_WAIT(1);
    __syncthreads();

    // ---- precompute ldmatrix per-lane addresses ----
    uint32_t aAddrBase[2], aSw[2];
    {
        int rl = warpM * 32 + (lane & 15);
        #pragma unroll
        for (int m = 0; m < 2; m++) {
            int r = rl + m * 16;
            aAddrBase[m] = sAu + (uint32_t)(r * AW) * 4u;
            aSw[m] = (uint32_t)((r & 7) << 2);
        }
    }
    const uint32_t khA4 = (uint32_t)((lane >> 4) << 2);
    // B local rows within this warp's 32-row slice
    uint32_t bAddrBase[2], bSw[2];
    {
        int nl = ((lane >> 4) << 3) + (lane & 7);        // 0..15
        #pragma unroll
        for (int p = 0; p < 2; p++) {
            int n = nl + p * 16;                         // 0..31 local
            bAddrBase[p] = (uint32_t)(n * BW) * 4u;
            bSw[p] = (uint32_t)((n & 7) << 2);
        }
    }
    const uint32_t khB4 = (uint32_t)(((lane >> 3) & 1) << 2);

    float acc[2][4][4];
    #pragma unroll
    for (int m = 0; m < 2; m++)
        #pragma unroll
        for (int nt = 0; nt < 4; nt++)
            #pragma unroll
            for (int q = 0; q < 4; q++) acc[m][nt][q] = 0.0f;

    float s0[4], s1[4], s2[4];
    int   i0[4], i1[4], i2[4];
    #pragma unroll
    for (int i = 0; i < 4; i++) {
        s0[i] = -2.0f; s1[i] = -2.0f; s2[i] = -2.0f;
        i0[i] = 0; i1[i] = 0; i2[i] = 0;
    }

    for (int c = 0; c < TOTCH; c++) {
        const uint32_t cb32 = (uint32_t)((c & 3) * 32);          // A k-offset words
        const uint32_t bBufByte = sBwu + (uint32_t)((c & 1) * 1024) * 4u;

        #pragma unroll
        for (int ks = 0; ks < 4; ks++) {
            const uint32_t ksw = (uint32_t)(ks * 8);
            uint32_t a[2][4];
            #pragma unroll
            for (int m = 0; m < 2; m++) {
                uint32_t woff = cb32 + ((ksw + khA4) ^ aSw[m]);
                ldm_x4(a[m], aAddrBase[m] + (woff << 2));
            }
            uint32_t bq[8];
            #pragma unroll
            for (int p = 0; p < 2; p++) {
                uint32_t woff = (ksw + khB4) ^ bSw[p];
                ldm_x4(&bq[p * 4], bBufByte + bAddrBase[p] + (woff << 2));
            }
            #pragma unroll
            for (int m = 0; m < 2; m++)
                #pragma unroll
                for (int nt = 0; nt < 4; nt++)
                    mma_bf16(acc[m][nt], a[m], &bq[nt * 2]);
        }

        // refill the buffer just consumed (program order keeps this safe),
        // then wait for next chunk's data (warp-scoped; no CTA barrier)
        if (c + 2 < TOTCH) issueB(c + 2);
        if (c + 1 < TOTCH) { CP_WAIT(1); __syncwarp(); }

        if ((c & 3) == 3) {
            const int tcol = bBase + (c >> 2) * BN + warpN * 32 + tx * 2;
            #pragma unroll
            for (int m = 0; m < 2; m++) {
                #pragma unroll
                for (int h = 0; h < 2; h++) {
                    const int sl = m * 2 + h;
                    float bm = acc[m][0][h * 2];
                    #pragma unroll
                    for (int nt = 0; nt < 4; nt++) {
                        bm = fmaxf(bm, acc[m][nt][h * 2 + 0]);
                        bm = fmaxf(bm, acc[m][nt][h * 2 + 1]);
                    }
                    if (bm > s2[sl]) {
                        #pragma unroll
                        for (int nt = 0; nt < 4; nt++) {
                            #pragma unroll
                            for (int p = 0; p < 2; p++) {
                                float v = acc[m][nt][h * 2 + p];
                                int col = tcol + nt * 8 + p;
                                if (v > s2[sl]) {
                                    if (v > s1[sl]) {
                                        if (v > s0[sl]) {
                                            s2[sl] = s1[sl]; i2[sl] = i1[sl];
                                            s1[sl] = s0[sl]; i1[sl] = i0[sl];
                                            s0[sl] = v;      i0[sl] = col;
                                        } else {
                                            s2[sl] = s1[sl]; i2[sl] = i1[sl];
                                            s1[sl] = v;      i1[sl] = col;
                                        }
                                    } else {
                                        s2[sl] = v; i2[sl] = col;
                                    }
                                }
                            }
                        }
                    }
                }
            }
            #pragma unroll
            for (int m = 0; m < 2; m++)
                #pragma unroll
                for (int nt = 0; nt < 4; nt++)
                    #pragma unroll
                    for (int q = 0; q < 4; q++) acc[m][nt][q] = 0.0f;
        }
    }

    // ---- CTA-level merge: 16 contributors per row -> top-3 (val+idx) ----
    __syncthreads();
    float* candV = (float*)smem;                 // [64][16][3]
    int*   candI = (int*)(smem + 3072);          // [64][16][3]
    #pragma unroll
    for (int m = 0; m < 2; m++) {
        #pragma unroll
        for (int h = 0; h < 2; h++) {
            const int sl = m * 2 + h;
            int row = warpM * 32 + m * 16 + h * 8 + ty;
            int ct  = warpN * 4 + tx;
            int o = (row * 16 + ct) * 3;
            candV[o + 0] = s0[sl]; candV[o + 1] = s1[sl]; candV[o + 2] = s2[sl];
            candI[o + 0] = i0[sl]; candI[o + 1] = i1[sl]; candI[o + 2] = i2[sl];
        }
    }
    __syncthreads();
    if (tid < BM) {
        const float* pv = candV + tid * 48;
        const int*   pi = candI + tid * 48;
        float t0 = -2.0f, t1 = -2.0f, t2 = -2.0f;
        int   j0 = 0, j1 = 0, j2 = 0;
        #pragma unroll
        for (int i = 0; i < 48; i++) {
            float v = pv[i]; int ix = pi[i];
            if (v > t2) {
                if (v > t1) {
                    if (v > t0) { t2 = t1; j2 = j1; t1 = t0; j1 = j0; t0 = v; j0 = ix; }
                    else        { t2 = t1; j2 = j1; t1 = v;  j1 = ix; }
                } else          { t2 = v; j2 = ix; }
            }
        }
        size_t row = (size_t)(blockIdx.x * BM + tid);
        size_t o = (row * SPLITS + blockIdx.y) * 3;
        partv[o + 0] = t0; partv[o + 1] = t1; partv[o + 2] = t2;
        parti[o + 0] = j0; parti[o + 1] = j1; parti[o + 2] = j2;
    }
}

// ---------------- final: top-8 of 48 candidates, exact fp32 rescore, mean top-3 ----
__device__ __forceinline__ unsigned long long mk_key(float v, int idx) {
    uint32_t u = __float_as_uint(v);
    u = (u & 0x80000000u) ? ~u : (u | 0x80000000u);
    return ((unsigned long long)u << 32) | (uint32_t)idx;
}

__global__ void rescore_top3(const float* __restrict__ partv, const int* __restrict__ parti,
                             const float* __restrict__ An, const float* __restrict__ Bn,
                             float* __restrict__ out) {
    const int warp = (blockIdx.x * blockDim.x + threadIdx.x) >> 5;
    const int lane = threadIdx.x & 31;
    if (warp >= N_ROWS) return;
    const int row = warp;

    const float* pv = partv + (size_t)row * 48;
    const int*   pi = parti + (size_t)row * 48;
    unsigned long long k0 = mk_key(pv[lane], pi[lane]);
    unsigned long long k1 = (lane < 16) ? mk_key(pv[32 + lane], pi[32 + lane]) : 0ull;

    int win[8];
    #pragma unroll
    for (int r = 0; r < 8; r++) {
        unsigned long long m = (k0 > k1) ? k0 : k1;
        #pragma unroll
        for (int o = 16; o > 0; o >>= 1) {
            unsigned long long t = __shfl_xor_sync(0xFFFFFFFFu, m, o);
            if (t > m) m = t;
        }
        win[r] = (int)(uint32_t)m;
        if (k0 == m) k0 = 0ull;
        if (k1 == m) k1 = 0ull;
    }

    const float4* a4 = (const float4*)(An + (size_t)row * DIM);
    float4 av0 = a4[lane * 2], av1 = a4[lane * 2 + 1];

    float dots[8];
    #pragma unroll
    for (int j = 0; j < 8; j++) {
        const float4* b4 = (const float4*)(Bn + (size_t)win[j] * DIM);
        float4 b0 = b4[lane * 2], b1 = b4[lane * 2 + 1];
        float p = av0.x * b0.x + av0.y * b0.y + av0.z * b0.z + av0.w * b0.w
                + av1.x * b1.x + av1.y * b1.y + av1.z * b1.z + av1.w * b1.w;
        #pragma unroll
        for (int o = 16; o > 0; o >>= 1) p += __shfl_xor_sync(0xFFFFFFFFu, p, o);
        dots[j] = p;
    }

    if (lane == 0) {
        float t0 = -2.0f, t1 = -2.0f, t2 = -2.0f;
        #pragma unroll
        for (int j = 0; j < 8; j++) {
            float v = dots[j];
            t2 = fmaxf(t2, fminf(v, t1));
            t1 = fmaxf(t1, fminf(v, t0));
            t0 = fmaxf(t0, v);
        }
        out[row] = (t0 + t1 + t2) * (1.0f / 3.0f);
    }
}

// ---------------- launcher ----------------
extern "C" void kernel_launch(void* const* d_in, const int* in_sizes, int n_in,
                              void* d_out, int out_size) {
    const float* A = (const float*)d_in[0];
    const float* B = (const float*)d_in[1];
    float* out = (float*)d_out;

    float* An;  cudaGetSymbolAddress((void**)&An,  g_An);
    float* Bn;  cudaGetSymbolAddress((void**)&Bn,  g_Bn);
    __nv_bfloat16* Ah; cudaGetSymbolAddress((void**)&Ah, g_Ah);
    __nv_bfloat16* Bh; cudaGetSymbolAddress((void**)&Bh, g_Bh);
    float* pv;  cudaGetSymbolAddress((void**)&pv, g_partv);
    int*   pi;  cudaGetSymbolAddress((void**)&pi, g_parti);

    cudaFuncSetAttribute(gemm_top3, cudaFuncAttributeMaxDynamicSharedMemorySize, SMEM_BYTES);

    normalize_rows<<<N_ROWS, DIM>>>(A, An, Ah);
    normalize_rows<<<M_ROWS, DIM>>>(B, Bn, Bh);

    dim3 grid(N_ROWS / BM, SPLITS);
    gemm_top3<<<grid, 256, SMEM_BYTES>>>(Ah, Bh, pv, pi);

    rescore_top3<<<N_ROWS * 32 / 256, 256>>>(pv, pi, An, Bn, out);
}

// round 13
// speedup vs baseline: 1.7941x; 1.5108x over previous
#include <cuda_runtime.h>
#include <cuda_fp16.h>
#include <cstdint>

// ---------------- problem shapes (fixed) ----------------
#define N_ROWS 8192
#define M_ROWS 16384
#define DIM    256

#define BM 64
#define BN 128
#define SPLITS 16
#define BROWS (M_ROWS / SPLITS)     // 1024
#define NBT   (BROWS / BN)          // 8 tiles
#define KCH   64                    // fp16 K-elems per chunk (128B/row)
#define CPT   (DIM / KCH)           // 4 chunks per tile
#define TOTCH (NBT * CPT)           // 32
#define NBUF  4

// smem (uint32 words): A = 64 rows x 128 words (32KB); B = 4 bufs x 128 rows x 32 words (64KB)
#define AW 128
#define BW 32
#define SMEM_WORDS (BM * AW + NBUF * BN * BW)   // 8192 + 16384 = 24576
#define SMEM_BYTES (SMEM_WORDS * 4)             // 98304 -> 2 CTAs/SM

// ---------------- scratch ----------------
__device__ float   g_An[N_ROWS * DIM];
__device__ float   g_Bn[M_ROWS * DIM];
__device__ __half  g_Ah[N_ROWS * DIM];
__device__ __half  g_Bh[M_ROWS * DIM];
__device__ float   g_partv[N_ROWS * SPLITS * 3];
__device__ int     g_parti[N_ROWS * SPLITS * 3];

// ---------------- helpers ----------------
__device__ __forceinline__ uint32_t smem_u32(const void* p) {
    uint32_t a;
    asm("{ .reg .u64 t; cvta.to.shared.u64 t, %1; cvt.u32.u64 %0, t; }" : "=r"(a) : "l"(p));
    return a;
}
__device__ __forceinline__ void cp_async16(uint32_t dst, const void* src) {
    asm volatile("cp.async.cg.shared.global [%0], [%1], 16;" :: "r"(dst), "l"(src));
}
#define CP_COMMIT()  asm volatile("cp.async.commit_group;" ::: "memory")
#define CP_WAIT(n)   asm volatile("cp.async.wait_group %0;" :: "n"(n) : "memory")

__device__ __forceinline__ void ldm_x4(uint32_t* r, uint32_t addr) {
    asm volatile("ldmatrix.sync.aligned.m8n8.x4.shared.b16 {%0,%1,%2,%3}, [%4];"
                 : "=r"(r[0]), "=r"(r[1]), "=r"(r[2]), "=r"(r[3]) : "r"(addr));
}
// fp16 inputs, fp16 accumulate (2 accumulator regs = 4 halves)
__device__ __forceinline__ void mma_f16(uint32_t* d, const uint32_t* a, const uint32_t* b) {
    asm volatile(
        "mma.sync.aligned.m16n8k16.row.col.f16.f16.f16.f16 "
        "{%0,%1},{%2,%3,%4,%5},{%6,%7},{%0,%1};"
        : "+r"(d[0]), "+r"(d[1])
        : "r"(a[0]), "r"(a[1]), "r"(a[2]), "r"(a[3]), "r"(b[0]), "r"(b[1]));
}

// ---------------- row L2 normalization: write fp32 (exact) + fp16 ----------------
__global__ void normalize_rows(const float* __restrict__ in,
                               float* __restrict__ outf,
                               __half* __restrict__ outh) {
    int row = blockIdx.x, tid = threadIdx.x;
    float v = in[row * DIM + tid];
    float s = v * v;
    #pragma unroll
    for (int o = 16; o > 0; o >>= 1) s += __shfl_xor_sync(0xFFFFFFFFu, s, o);
    __shared__ float red[8];
    if ((tid & 31) == 0) red[tid >> 5] = s;
    __syncthreads();
    __shared__ float tot;
    if (tid < 32) {
        float t = (tid < 8) ? red[tid] : 0.0f;
        #pragma unroll
        for (int o = 4; o > 0; o >>= 1) t += __shfl_xor_sync(0xFFFFFFFFu, t, o);
        if (tid == 0) tot = t;
    }
    __syncthreads();
    float y = v * rsqrtf(tot);
    outf[row * DIM + tid] = y;
    outh[row * DIM + tid] = __float2half(y);
}

// ---------------- fp16 mma GEMM (fp16 acc, ldmatrix, occ=2) + top-3 with indices ----------------
__global__ void __launch_bounds__(256, 2)
gemm_top3(const __half* __restrict__ Ah, const __half* __restrict__ Bh,
          float* __restrict__ partv, int* __restrict__ parti) {
    extern __shared__ uint32_t smem[];
    uint32_t* sA = smem;
    uint32_t* sB = smem + BM * AW;
    const uint32_t sAu = smem_u32(sA);
    const uint32_t sBu = smem_u32(sB);

    const int tid  = threadIdx.x;
    const int w    = tid >> 5, lane = tid & 31;
    const int ty   = lane >> 2, tx = lane & 3;
    const int warpM = w >> 2, warpN = w & 3;      // 2 x 4 warp grid

    const int aBase = blockIdx.x * BM;
    const int bBase = blockIdx.y * BROWS;

    // ---- A tile: 64 rows x 256 fp16; word-swizzle iw' = iw ^ ((r&7)<<2) ----
    #pragma unroll 4
    for (int i = tid; i < BM * 32; i += 256) {          // 16B units
        int r = i >> 5, f = i & 31;
        uint32_t dw = (uint32_t)(r * AW + ((4 * f) ^ ((r & 7) << 2)));
        cp_async16(sAu + dw * 4, Ah + (size_t)(aBase + r) * DIM + f * 8);
    }
    CP_COMMIT();

    auto issueB = [&](int c) {
        int t = c >> 2, kc = c & 3, buf = c & 3;
        #pragma unroll 4
        for (int i = tid; i < BN * 8; i += 256) {       // 16B units
            int n = i >> 3, f = i & 7;
            uint32_t dw = (uint32_t)(buf * BN * BW + n * BW + ((4 * f) ^ ((n & 7) << 2)));
            cp_async16(sBu + dw * 4,
                       Bh + (size_t)(bBase + t * BN + n) * DIM + kc * KCH + f * 8);
        }
        CP_COMMIT();
    };

    issueB(0); issueB(1); issueB(2);

    // ---- precompute ldmatrix per-lane addresses ----
    uint32_t aAddrBase[2], aSw[2];
    {
        int rl = warpM * 32 + (lane & 15);
        #pragma unroll
        for (int m = 0; m < 2; m++) {
            int r = rl + m * 16;
            aAddrBase[m] = sAu + (uint32_t)(r * AW) * 4u;
            aSw[m] = (uint32_t)((r & 7) << 2);
        }
    }
    const uint32_t khA4 = (uint32_t)((lane >> 4) << 2);
    uint32_t bAddrBase[2], bSw[2];
    {
        int nl = warpN * 32 + ((lane >> 4) << 3) + (lane & 7);
        #pragma unroll
        for (int p = 0; p < 2; p++) {
            int n = nl + p * 16;
            bAddrBase[p] = (uint32_t)(n * BW) * 4u;
            bSw[p] = (uint32_t)((n & 7) << 2);
        }
    }
    const uint32_t khB4 = (uint32_t)(((lane >> 3) & 1) << 2);

    uint32_t acc[2][4][2];                         // fp16x2 accumulators
    #pragma unroll
    for (int m = 0; m < 2; m++)
        #pragma unroll
        for (int nt = 0; nt < 4; nt++) { acc[m][nt][0] = 0u; acc[m][nt][1] = 0u; }

    float s0[4], s1[4], s2[4];
    int   i0[4], i1[4], i2[4];
    #pragma unroll
    for (int i = 0; i < 4; i++) {
        s0[i] = -2.0f; s1[i] = -2.0f; s2[i] = -2.0f;
        i0[i] = 0; i1[i] = 0; i2[i] = 0;
    }

    for (int c = 0; c < TOTCH; c++) {
        CP_WAIT(2);                  // group c complete (pending <= {c+1, c+2})
        __syncthreads();             // all threads done with buf (c+3)%4's previous contents
        if (c + 3 < TOTCH) issueB(c + 3);
        else CP_COMMIT();

        const uint32_t cb32 = (uint32_t)((c & 3) * 32);
        const uint32_t bBufByte = sBu + (uint32_t)((c & 3) * BN * BW) * 4u;

        #pragma unroll
        for (int ks = 0; ks < 4; ks++) {
            const uint32_t ksw = (uint32_t)(ks * 8);
            uint32_t a[2][4];
            #pragma unroll
            for (int m = 0; m < 2; m++) {
                uint32_t woff = cb32 + ((ksw + khA4) ^ aSw[m]);
                ldm_x4(a[m], aAddrBase[m] + (woff << 2));
            }
            uint32_t bq[8];
            #pragma unroll
            for (int p = 0; p < 2; p++) {
                uint32_t woff = (ksw + khB4) ^ bSw[p];
                ldm_x4(&bq[p * 4], bBufByte + bAddrBase[p] + (woff << 2));
            }
            #pragma unroll
            for (int m = 0; m < 2; m++)
                #pragma unroll
                for (int nt = 0; nt < 4; nt++)
                    mma_f16(acc[m][nt], a[m], &bq[nt * 2]);
        }

        if ((c & 3) == 3) {
            const int tcol = bBase + (c >> 2) * BN + warpN * 32 + tx * 2;
            #pragma unroll
            for (int m = 0; m < 2; m++) {
                #pragma unroll
                for (int h = 0; h < 2; h++) {
                    const int sl = m * 2 + h;
                    float v[8];
                    #pragma unroll
                    for (int nt = 0; nt < 4; nt++) {
                        __half2 hv = *reinterpret_cast<const __half2*>(&acc[m][nt][h]);
                        float2 f = __half22float2(hv);
                        v[nt * 2 + 0] = f.x;
                        v[nt * 2 + 1] = f.y;
                    }
                    float bm = v[0];
                    #pragma unroll
                    for (int q = 1; q < 8; q++) bm = fmaxf(bm, v[q]);
                    if (bm > s2[sl]) {
                        #pragma unroll
                        for (int nt = 0; nt < 4; nt++) {
                            #pragma unroll
                            for (int p = 0; p < 2; p++) {
                                float x = v[nt * 2 + p];
                                int col = tcol + nt * 8 + p;
                                if (x > s2[sl]) {
                                    if (x > s1[sl]) {
                                        if (x > s0[sl]) {
                                            s2[sl] = s1[sl]; i2[sl] = i1[sl];
                                            s1[sl] = s0[sl]; i1[sl] = i0[sl];
                                            s0[sl] = x;      i0[sl] = col;
                                        } else {
                                            s2[sl] = s1[sl]; i2[sl] = i1[sl];
                                            s1[sl] = x;      i1[sl] = col;
                                        }
                                    } else {
                                        s2[sl] = x; i2[sl] = col;
                                    }
                                }
                            }
                        }
                    }
                }
            }
            #pragma unroll
            for (int m = 0; m < 2; m++)
                #pragma unroll
                for (int nt = 0; nt < 4; nt++) { acc[m][nt][0] = 0u; acc[m][nt][1] = 0u; }
        }
    }

    // ---- CTA-level merge: 16 contributors per row -> top-3 (val+idx) ----
    __syncthreads();
    float* candV = (float*)smem;                 // [64][16][3]
    int*   candI = (int*)(smem + 3072);          // [64][16][3]
    #pragma unroll
    for (int m = 0; m < 2; m++) {
        #pragma unroll
        for (int h = 0; h < 2; h++) {
            const int sl = m * 2 + h;
            int row = warpM * 32 + m * 16 + h * 8 + ty;
            int ct  = warpN * 4 + tx;
            int o = (row * 16 + ct) * 3;
            candV[o + 0] = s0[sl]; candV[o + 1] = s1[sl]; candV[o + 2] = s2[sl];
            candI[o + 0] = i0[sl]; candI[o + 1] = i1[sl]; candI[o + 2] = i2[sl];
        }
    }
    __syncthreads();
    if (tid < BM) {
        const float* pv = candV + tid * 48;
        const int*   pi = candI + tid * 48;
        float t0 = -2.0f, t1 = -2.0f, t2 = -2.0f;
        int   j0 = 0, j1 = 0, j2 = 0;
        #pragma unroll
        for (int i = 0; i < 48; i++) {
            float v = pv[i]; int ix = pi[i];
            if (v > t2) {
                if (v > t1) {
                    if (v > t0) { t2 = t1; j2 = j1; t1 = t0; j1 = j0; t0 = v; j0 = ix; }
                    else        { t2 = t1; j2 = j1; t1 = v;  j1 = ix; }
                } else          { t2 = v; j2 = ix; }
            }
        }
        size_t row = (size_t)(blockIdx.x * BM + tid);
        size_t o = (row * SPLITS + blockIdx.y) * 3;
        partv[o + 0] = t0; partv[o + 1] = t1; partv[o + 2] = t2;
        parti[o + 0] = j0; parti[o + 1] = j1; parti[o + 2] = j2;
    }
}

// ---------------- final: top-8 of 48 candidates, exact fp32 rescore, mean top-3 ----
__device__ __forceinline__ unsigned long long mk_key(float v, int idx) {
    uint32_t u = __float_as_uint(v);
    u = (u & 0x80000000u) ? ~u : (u | 0x80000000u);
    return ((unsigned long long)u << 32) | (uint32_t)idx;
}

__global__ void rescore_top3(const float* __restrict__ partv, const int* __restrict__ parti,
                             const float* __restrict__ An, const float* __restrict__ Bn,
                             float* __restrict__ out) {
    const int warp = (blockIdx.x * blockDim.x + threadIdx.x) >> 5;
    const int lane = threadIdx.x & 31;
    if (warp >= N_ROWS) return;
    const int row = warp;

    const float* pv = partv + (size_t)row * 48;
    const int*   pi = parti + (size_t)row * 48;
    unsigned long long k0 = mk_key(pv[lane], pi[lane]);
    unsigned long long k1 = (lane < 16) ? mk_key(pv[32 + lane], pi[32 + lane]) : 0ull;

    int win[8];
    #pragma unroll
    for (int r = 0; r < 8; r++) {
        unsigned long long m = (k0 > k1) ? k0 : k1;
        #pragma unroll
        for (int o = 16; o > 0; o >>= 1) {
            unsigned long long t = __shfl_xor_sync(0xFFFFFFFFu, m, o);
            if (t > m) m = t;
        }
        win[r] = (int)(uint32_t)m;
        if (k0 == m) k0 = 0ull;
        if (k1 == m) k1 = 0ull;
    }

    const float4* a4 = (const float4*)(An + (size_t)row * DIM);
    float4 av0 = a4[lane * 2], av1 = a4[lane * 2 + 1];

    float dots[8];
    #pragma unroll
    for (int j = 0; j < 8; j++) {
        const float4* b4 = (const float4*)(Bn + (size_t)win[j] * DIM);
        float4 b0 = b4[lane * 2], b1 = b4[lane * 2 + 1];
        float p = av0.x * b0.x + av0.y * b0.y + av0.z * b0.z + av0.w * b0.w
                + av1.x * b1.x + av1.y * b1.y + av1.z * b1.z + av1.w * b1.w;
        #pragma unroll
        for (int o = 16; o > 0; o >>= 1) p += __shfl_xor_sync(0xFFFFFFFFu, p, o);
        dots[j] = p;
    }

    if (lane == 0) {
        float t0 = -2.0f, t1 = -2.0f, t2 = -2.0f;
        #pragma unroll
        for (int j = 0; j < 8; j++) {
            float v = dots[j];
            t2 = fmaxf(t2, fminf(v, t1));
            t1 = fmaxf(t1, fminf(v, t0));
            t0 = fmaxf(t0, v);
        }
        out[row] = (t0 + t1 + t2) * (1.0f / 3.0f);
    }
}

// ---------------- launcher ----------------
extern "C" void kernel_launch(void* const* d_in, const int* in_sizes, int n_in,
                              void* d_out, int out_size) {
    const float* A = (const float*)d_in[0];
    const float* B = (const float*)d_in[1];
    float* out = (float*)d_out;

    float* An;  cudaGetSymbolAddress((void**)&An,  g_An);
    float* Bn;  cudaGetSymbolAddress((void**)&Bn,  g_Bn);
    __half* Ah; cudaGetSymbolAddress((void**)&Ah, g_Ah);
    __half* Bh; cudaGetSymbolAddress((void**)&Bh, g_Bh);
    float* pv;  cudaGetSymbolAddress((void**)&pv, g_partv);
    int*   pi;  cudaGetSymbolAddress((void**)&pi, g_parti);

    cudaFuncSetAttribute(gemm_top3, cudaFuncAttributeMaxDynamicSharedMemorySize, SMEM_BYTES);

    normalize_rows<<<N_ROWS, DIM>>>(A, An, Ah);
    normalize_rows<<<M_ROWS, DIM>>>(B, Bn, Bh);

    dim3 grid(N_ROWS / BM, SPLITS);
    gemm_top3<<<grid, 256, SMEM_BYTES>>>(Ah, Bh, pv, pi);

    rescore_top3<<<N_ROWS * 32 / 256, 256>>>(pv, pi, An, Bn, out);
}

// round 14
// speedup vs baseline: 1.8161x; 1.0122x over previous
#include <cuda_runtime.h>
#include <cuda_fp16.h>
#include <cstdint>

// ---------------- problem shapes (fixed) ----------------
#define N_ROWS 8192
#define M_ROWS 16384
#define DIM    256

#define BM 64
#define BN 128
#define SPLITS 16
#define BROWS (M_ROWS / SPLITS)     // 1024
#define NBT   (BROWS / BN)          // 8 tiles
#define KCH   64                    // fp16 K-elems per chunk (128B/row)
#define CPT   (DIM / KCH)           // 4 chunks per tile
#define TOTCH (NBT * CPT)           // 32
#define NBUF  4

// smem (uint32 words): A = 64 rows x 128 words (32KB); B = 4 bufs x 128 rows x 32 words (64KB)
#define AW 128
#define BW 32
#define SMEM_WORDS (BM * AW + NBUF * BN * BW)   // 24576
#define SMEM_BYTES (SMEM_WORDS * 4)             // 98304 -> 2 CTAs/SM

// ---------------- scratch ----------------
__device__ float   g_An[N_ROWS * DIM];          // normalized A (fp32, for exact rescore)
__device__ __half  g_Ah[N_ROWS * DIM];
__device__ __half  g_Bh[M_ROWS * DIM];
__device__ float   g_partv[N_ROWS * SPLITS * 3];
__device__ int     g_parti[N_ROWS * SPLITS * 3];

// ---------------- helpers ----------------
__device__ __forceinline__ uint32_t smem_u32(const void* p) {
    uint32_t a;
    asm("{ .reg .u64 t; cvta.to.shared.u64 t, %1; cvt.u32.u64 %0, t; }" : "=r"(a) : "l"(p));
    return a;
}
__device__ __forceinline__ void cp_async16(uint32_t dst, const void* src) {
    asm volatile("cp.async.cg.shared.global [%0], [%1], 16;" :: "r"(dst), "l"(src));
}
#define CP_COMMIT()  asm volatile("cp.async.commit_group;" ::: "memory")
#define CP_WAIT(n)   asm volatile("cp.async.wait_group %0;" :: "n"(n) : "memory")

__device__ __forceinline__ void ldm_x4(uint32_t* r, uint32_t addr) {
    asm volatile("ldmatrix.sync.aligned.m8n8.x4.shared.b16 {%0,%1,%2,%3}, [%4];"
                 : "=r"(r[0]), "=r"(r[1]), "=r"(r[2]), "=r"(r[3]) : "r"(addr));
}
__device__ __forceinline__ void mma_f16(uint32_t* d, const uint32_t* a, const uint32_t* b) {
    asm volatile(
        "mma.sync.aligned.m16n8k16.row.col.f16.f16.f16.f16 "
        "{%0,%1},{%2,%3,%4,%5},{%6,%7},{%0,%1};"
        : "+r"(d[0]), "+r"(d[1])
        : "r"(a[0]), "r"(a[1]), "r"(a[2]), "r"(a[3]), "r"(b[0]), "r"(b[1]));
}

// ---------------- row L2 normalization ----------------
__global__ void normalize_rows_full(const float* __restrict__ in,
                                    float* __restrict__ outf,
                                    __half* __restrict__ outh) {
    int row = blockIdx.x, tid = threadIdx.x;
    float v = in[row * DIM + tid];
    float s = v * v;
    #pragma unroll
    for (int o = 16; o > 0; o >>= 1) s += __shfl_xor_sync(0xFFFFFFFFu, s, o);
    __shared__ float red[8];
    if ((tid & 31) == 0) red[tid >> 5] = s;
    __syncthreads();
    __shared__ float tot;
    if (tid < 32) {
        float t = (tid < 8) ? red[tid] : 0.0f;
        #pragma unroll
        for (int o = 4; o > 0; o >>= 1) t += __shfl_xor_sync(0xFFFFFFFFu, t, o);
        if (tid == 0) tot = t;
    }
    __syncthreads();
    float y = v * rsqrtf(tot);
    outf[row * DIM + tid] = y;
    outh[row * DIM + tid] = __float2half(y);
}

__global__ void normalize_rows_h(const float* __restrict__ in,
                                 __half* __restrict__ outh) {
    int row = blockIdx.x, tid = threadIdx.x;
    float v = in[row * DIM + tid];
    float s = v * v;
    #pragma unroll
    for (int o = 16; o > 0; o >>= 1) s += __shfl_xor_sync(0xFFFFFFFFu, s, o);
    __shared__ float red[8];
    if ((tid & 31) == 0) red[tid >> 5] = s;
    __syncthreads();
    __shared__ float tot;
    if (tid < 32) {
        float t = (tid < 8) ? red[tid] : 0.0f;
        #pragma unroll
        for (int o = 4; o > 0; o >>= 1) t += __shfl_xor_sync(0xFFFFFFFFu, t, o);
        if (tid == 0) tot = t;
    }
    __syncthreads();
    outh[row * DIM + tid] = __float2half(v * rsqrtf(tot));
}

// ---------------- fp16 mma GEMM (fp16 acc, pipelined frags, occ=2) + top-3 ----------------
__global__ void __launch_bounds__(256, 2)
gemm_top3(const __half* __restrict__ Ah, const __half* __restrict__ Bh,
          float* __restrict__ partv, int* __restrict__ parti) {
    extern __shared__ uint32_t smem[];
    uint32_t* sA = smem;
    uint32_t* sB = smem + BM * AW;
    const uint32_t sAu = smem_u32(sA);
    const uint32_t sBu = smem_u32(sB);

    const int tid  = threadIdx.x;
    const int w    = tid >> 5, lane = tid & 31;
    const int ty   = lane >> 2, tx = lane & 3;
    const int warpM = w >> 2, warpN = w & 3;      // 2 x 4 warp grid

    const int aBase = blockIdx.x * BM;
    const int bBase = blockIdx.y * BROWS;

    // ---- A tile: 64 rows x 256 fp16; word-swizzle iw' = iw ^ ((r&7)<<2) ----
    #pragma unroll 4
    for (int i = tid; i < BM * 32; i += 256) {          // 16B units
        int r = i >> 5, f = i & 31;
        uint32_t dw = (uint32_t)(r * AW + ((4 * f) ^ ((r & 7) << 2)));
        cp_async16(sAu + dw * 4, Ah + (size_t)(aBase + r) * DIM + f * 8);
    }
    CP_COMMIT();

    auto issueB = [&](int c) {
        int t = c >> 2, kc = c & 3, buf = c & 3;
        #pragma unroll 4
        for (int i = tid; i < BN * 8; i += 256) {       // 16B units
            int n = i >> 3, f = i & 7;
            uint32_t dw = (uint32_t)(buf * BN * BW + n * BW + ((4 * f) ^ ((n & 7) << 2)));
            cp_async16(sBu + dw * 4,
                       Bh + (size_t)(bBase + t * BN + n) * DIM + kc * KCH + f * 8);
        }
        CP_COMMIT();
    };

    issueB(0); issueB(1); issueB(2);

    // ---- precompute ldmatrix per-lane addresses ----
    uint32_t aAddrBase[2], aSw[2];
    {
        int rl = warpM * 32 + (lane & 15);
        #pragma unroll
        for (int m = 0; m < 2; m++) {
            int r = rl + m * 16;
            aAddrBase[m] = sAu + (uint32_t)(r * AW) * 4u;
            aSw[m] = (uint32_t)((r & 7) << 2);
        }
    }
    const uint32_t khA4 = (uint32_t)((lane >> 4) << 2);
    uint32_t bAddrBase[2], bSw[2];
    {
        int nl = warpN * 32 + ((lane >> 4) << 3) + (lane & 7);
        #pragma unroll
        for (int p = 0; p < 2; p++) {
            int n = nl + p * 16;
            bAddrBase[p] = (uint32_t)(n * BW) * 4u;
            bSw[p] = (uint32_t)((n & 7) << 2);
        }
    }
    const uint32_t khB4 = (uint32_t)(((lane >> 3) & 1) << 2);

    uint32_t acc[2][4][2];                         // fp16x2 accumulators
    #pragma unroll
    for (int m = 0; m < 2; m++)
        #pragma unroll
        for (int nt = 0; nt < 4; nt++) { acc[m][nt][0] = 0u; acc[m][nt][1] = 0u; }

    float s0[4], s1[4], s2[4];
    int   i0[4], i1[4], i2[4];
    #pragma unroll
    for (int i = 0; i < 4; i++) {
        s0[i] = -2.0f; s1[i] = -2.0f; s2[i] = -2.0f;
        i0[i] = 0; i1[i] = 0; i2[i] = 0;
    }

    // fragment double buffers
    uint32_t afr[2][2][4];
    uint32_t bfr[2][8];

    auto loadFrags = [&](int buf, uint32_t cb32, uint32_t bBufByte, int ks) {
        const uint32_t ksw = (uint32_t)(ks * 8);
        #pragma unroll
        for (int m = 0; m < 2; m++) {
            uint32_t woff = cb32 + ((ksw + khA4) ^ aSw[m]);
            ldm_x4(afr[buf][m], aAddrBase[m] + (woff << 2));
        }
        #pragma unroll
        for (int p = 0; p < 2; p++) {
            uint32_t woff = (ksw + khB4) ^ bSw[p];
            ldm_x4(&bfr[buf][p * 4], bBufByte + bAddrBase[p] + (woff << 2));
        }
    };

    for (int c = 0; c < TOTCH; c++) {
        CP_WAIT(2);                  // group c complete (pending <= {c+1, c+2})
        __syncthreads();             // all threads done with buf (c+3)%4's previous contents

        const uint32_t cb32 = (uint32_t)((c & 3) * 32);
        const uint32_t bBufByte = sBu + (uint32_t)((c & 3) * BN * BW) * 4u;

        loadFrags(0, cb32, bBufByte, 0);           // prime ks=0
        if (c + 3 < TOTCH) issueB(c + 3);
        else CP_COMMIT();

        #pragma unroll
        for (int ks = 0; ks < 4; ks++) {
            const int cur = ks & 1;
            if (ks < 3) loadFrags(cur ^ 1, cb32, bBufByte, ks + 1);
            #pragma unroll
            for (int m = 0; m < 2; m++)
                #pragma unroll
                for (int nt = 0; nt < 4; nt++)
                    mma_f16(acc[m][nt], afr[cur][m], &bfr[cur][nt * 2]);
        }

        if ((c & 3) == 3) {
            const int tcol = bBase + (c >> 2) * BN + warpN * 32 + tx * 2;
            #pragma unroll
            for (int m = 0; m < 2; m++) {
                #pragma unroll
                for (int h = 0; h < 2; h++) {
                    const int sl = m * 2 + h;
                    float v[8];
                    #pragma unroll
                    for (int nt = 0; nt < 4; nt++) {
                        __half2 hv = *reinterpret_cast<const __half2*>(&acc[m][nt][h]);
                        float2 f = __half22float2(hv);
                        v[nt * 2 + 0] = f.x;
                        v[nt * 2 + 1] = f.y;
                    }
                    float bm = v[0];
                    #pragma unroll
                    for (int q = 1; q < 8; q++) bm = fmaxf(bm, v[q]);
                    if (bm > s2[sl]) {
                        #pragma unroll
                        for (int nt = 0; nt < 4; nt++) {
                            #pragma unroll
                            for (int p = 0; p < 2; p++) {
                                float x = v[nt * 2 + p];
                                int col = tcol + nt * 8 + p;
                                if (x > s2[sl]) {
                                    if (x > s1[sl]) {
                                        if (x > s0[sl]) {
                                            s2[sl] = s1[sl]; i2[sl] = i1[sl];
                                            s1[sl] = s0[sl]; i1[sl] = i0[sl];
                                            s0[sl] = x;      i0[sl] = col;
                                        } else {
                                            s2[sl] = s1[sl]; i2[sl] = i1[sl];
                                            s1[sl] = x;      i1[sl] = col;
                                        }
                                    } else {
                                        s2[sl] = x; i2[sl] = col;
                                    }
                                }
                            }
                        }
                    }
                }
            }
            #pragma unroll
            for (int m = 0; m < 2; m++)
                #pragma unroll
                for (int nt = 0; nt < 4; nt++) { acc[m][nt][0] = 0u; acc[m][nt][1] = 0u; }
        }
    }

    // ---- CTA-level merge: 16 contributors per row -> top-3 (val+idx) ----
    __syncthreads();
    float* candV = (float*)smem;                 // [64][16][3]
    int*   candI = (int*)(smem + 3072);          // [64][16][3]
    #pragma unroll
    for (int m = 0; m < 2; m++) {
        #pragma unroll
        for (int h = 0; h < 2; h++) {
            const int sl = m * 2 + h;
            int row = warpM * 32 + m * 16 + h * 8 + ty;
            int ct  = warpN * 4 + tx;
            int o = (row * 16 + ct) * 3;
            candV[o + 0] = s0[sl]; candV[o + 1] = s1[sl]; candV[o + 2] = s2[sl];
            candI[o + 0] = i0[sl]; candI[o + 1] = i1[sl]; candI[o + 2] = i2[sl];
        }
    }
    __syncthreads();
    if (tid < BM) {
        const float* pv = candV + tid * 48;
        const int*   pi = candI + tid * 48;
        float t0 = -2.0f, t1 = -2.0f, t2 = -2.0f;
        int   j0 = 0, j1 = 0, j2 = 0;
        #pragma unroll
        for (int i = 0; i < 48; i++) {
            float v = pv[i]; int ix = pi[i];
            if (v > t2) {
                if (v > t1) {
                    if (v > t0) { t2 = t1; j2 = j1; t1 = t0; j1 = j0; t0 = v; j0 = ix; }
                    else        { t2 = t1; j2 = j1; t1 = v;  j1 = ix; }
                } else          { t2 = v; j2 = ix; }
            }
        }
        size_t row = (size_t)(blockIdx.x * BM + tid);
        size_t o = (row * SPLITS + blockIdx.y) * 3;
        partv[o + 0] = t0; partv[o + 1] = t1; partv[o + 2] = t2;
        parti[o + 0] = j0; parti[o + 1] = j1; parti[o + 2] = j2;
    }
}

// ---------------- final: top-8 of 48 candidates, exact fp32 rescore, mean top-3 ----
__device__ __forceinline__ unsigned long long mk_key(float v, int idx) {
    uint32_t u = __float_as_uint(v);
    u = (u & 0x80000000u) ? ~u : (u | 0x80000000u);
    return ((unsigned long long)u << 32) | (uint32_t)idx;
}

__global__ void rescore_top3(const float* __restrict__ partv, const int* __restrict__ parti,
                             const float* __restrict__ An, const float* __restrict__ Braw,
                             float* __restrict__ out) {
    const int warp = (blockIdx.x * blockDim.x + threadIdx.x) >> 5;
    const int lane = threadIdx.x & 31;
    if (warp >= N_ROWS) return;
    const int row = warp;

    const float* pv = partv + (size_t)row * 48;
    const int*   pi = parti + (size_t)row * 48;
    unsigned long long k0 = mk_key(pv[lane], pi[lane]);
    unsigned long long k1 = (lane < 16) ? mk_key(pv[32 + lane], pi[32 + lane]) : 0ull;

    int win[8];
    #pragma unroll
    for (int r = 0; r < 8; r++) {
        unsigned long long m = (k0 > k1) ? k0 : k1;
        #pragma unroll
        for (int o = 16; o > 0; o >>= 1) {
            unsigned long long t = __shfl_xor_sync(0xFFFFFFFFu, m, o);
            if (t > m) m = t;
        }
        win[r] = (int)(uint32_t)m;
        if (k0 == m) k0 = 0ull;
        if (k1 == m) k1 = 0ull;
    }

    const float4* a4 = (const float4*)(An + (size_t)row * DIM);
    float4 av0 = a4[lane * 2], av1 = a4[lane * 2 + 1];

    float dots[8];
    #pragma unroll
    for (int j = 0; j < 8; j++) {
        const float4* b4 = (const float4*)(Braw + (size_t)win[j] * DIM);
        float4 b0 = b4[lane * 2], b1 = b4[lane * 2 + 1];
        float p = av0.x * b0.x + av0.y * b0.y + av0.z * b0.z + av0.w * b0.w
                + av1.x * b1.x + av1.y * b1.y + av1.z * b1.z + av1.w * b1.w;
        float q = b0.x * b0.x + b0.y * b0.y + b0.z * b0.z + b0.w * b0.w
                + b1.x * b1.x + b1.y * b1.y + b1.z * b1.z + b1.w * b1.w;
        #pragma unroll
        for (int o = 16; o > 0; o >>= 1) {
            p += __shfl_xor_sync(0xFFFFFFFFu, p, o);
            q += __shfl_xor_sync(0xFFFFFFFFu, q, o);
        }
        dots[j] = p * rsqrtf(q);
    }

    if (lane == 0) {
        float t0 = -2.0f, t1 = -2.0f, t2 = -2.0f;
        #pragma unroll
        for (int j = 0; j < 8; j++) {
            float v = dots[j];
            t2 = fmaxf(t2, fminf(v, t1));
            t1 = fmaxf(t1, fminf(v, t0));
            t0 = fmaxf(t0, v);
        }
        out[row] = (t0 + t1 + t2) * (1.0f / 3.0f);
    }
}

// ---------------- launcher ----------------
extern "C" void kernel_launch(void* const* d_in, const int* in_sizes, int n_in,
                              void* d_out, int out_size) {
    const float* A = (const float*)d_in[0];
    const float* B = (const float*)d_in[1];
    float* out = (float*)d_out;

    float* An;  cudaGetSymbolAddress((void**)&An,  g_An);
    __half* Ah; cudaGetSymbolAddress((void**)&Ah, g_Ah);
    __half* Bh; cudaGetSymbolAddress((void**)&Bh, g_Bh);
    float* pv;  cudaGetSymbolAddress((void**)&pv, g_partv);
    int*   pi;  cudaGetSymbolAddress((void**)&pi, g_parti);

    cudaFuncSetAttribute(gemm_top3, cudaFuncAttributeMaxDynamicSharedMemorySize, SMEM_BYTES);

    normalize_rows_full<<<N_ROWS, DIM>>>(A, An, Ah);
    normalize_rows_h<<<M_ROWS, DIM>>>(B, Bh);

    dim3 grid(N_ROWS / BM, SPLITS);
    gemm_top3<<<grid, 256, SMEM_BYTES>>>(Ah, Bh, pv, pi);

    rescore_top3<<<N_ROWS * 32 / 256, 256>>>(pv, pi, An, B, out);
}